// round 5
// baseline (speedup 1.0000x reference)
#include <cuda_runtime.h>
#include <math.h>

#define B_  2
#define L_  512
#define H_  128
#define NH_ 2
#define DH_ 64

// Scratch (allocation-free rule: __device__ globals)
__device__ float g_Q[B_ * L_ * H_];
__device__ float g_K[B_ * L_ * H_];
__device__ float g_V[B_ * L_ * H_];
__device__ float g_O[B_ * L_ * H_];

#define TM 8   // rows per GEMM block

// ---------------------------------------------------------------------------
// Kernel 1: fused QKV projections. grid = (128, 3). blockIdx.y selects matrix.
//   Y = X @ W^T + b  (+ E[pos] for K and V)
// 128 threads, one output channel each, TM rows, float4-vectorized.
// ---------------------------------------------------------------------------
__global__ __launch_bounds__(128) void qkv_kernel(
    const float* __restrict__ query, const float* __restrict__ key,
    const float* __restrict__ value,
    const float* __restrict__ Wq, const float* __restrict__ bq,
    const float* __restrict__ Wk, const float* __restrict__ bk,
    const float* __restrict__ Wv, const float* __restrict__ bv,
    const float* __restrict__ E_PK, const float* __restrict__ E_PV,
    const int* __restrict__ poss)
{
    const int m = blockIdx.y;
    const float *X, *W, *bias, *E;
    float* Y;
    if (m == 0)      { X = query; W = Wq; bias = bq; E = nullptr; Y = g_Q; }
    else if (m == 1) { X = key;   W = Wk; bias = bk; E = E_PK;    Y = g_K; }
    else             { X = value; W = Wv; bias = bv; E = E_PV;    Y = g_V; }

    __shared__ float4 xs[TM][32];   // TM rows x 128 floats

    const int r0 = blockIdx.x * TM;
    const int o  = threadIdx.x;     // output channel 0..127

    const float4* Xv = (const float4*)(X + (size_t)r0 * H_);
    #pragma unroll
    for (int t = 0; t < (TM * 32) / 128; t++)
        ((float4*)xs)[o + t * 128] = Xv[o + t * 128];
    __syncthreads();

    float acc[TM];
    {
        float bb = bias[o];
        #pragma unroll
        for (int rr = 0; rr < TM; rr++) {
            acc[rr] = bb;
            if (E) acc[rr] += E[(size_t)poss[r0 + rr] * H_ + o];
        }
    }

    const float4* w4p = (const float4*)(W + (size_t)o * H_);
    #pragma unroll 4
    for (int c = 0; c < 32; c++) {
        float4 w = w4p[c];
        #pragma unroll
        for (int rr = 0; rr < TM; rr++) {
            float4 x = xs[rr][c];
            acc[rr] = fmaf(w.x, x.x, acc[rr]);
            acc[rr] = fmaf(w.y, x.y, acc[rr]);
            acc[rr] = fmaf(w.z, x.z, acc[rr]);
            acc[rr] = fmaf(w.w, x.w, acc[rr]);
        }
    }

    #pragma unroll
    for (int rr = 0; rr < TM; rr++)
        Y[(size_t)(r0 + rr) * H_ + o] = acc[rr];
}

// ---------------------------------------------------------------------------
// Kernel 2: attention. Warp-private pipeline: warp = one query row.
// Block handles TWO query tiles (t and 63-t) so per-warp/per-block work is
// nearly constant (~512 key iterations) despite the causal mask.
// grid = (32, NH, B), 256 threads (8 warps = 8 queries per tile).
// ---------------------------------------------------------------------------
#define TQ 8

__global__ __launch_bounds__(256) void attn_kernel(
    const float* __restrict__ E_RK, const float* __restrict__ E_RV,
    const int* __restrict__ interval)
{
    const int tpair = blockIdx.x;   // 0..31
    const int h = blockIdx.y;
    const int b = blockIdx.z;
    const int warp = threadIdx.x >> 5;
    const int lane = threadIdx.x & 31;
    const int hd = h * DH_;
    const int q = warp;             // warp-private query slot

    __shared__ float sc[TQ][L_];    // 16 KB: scores -> weights
    __shared__ int   idxs[TQ][L_];  // 16 KB: interval indices

    const float* Kb = g_K + (size_t)b * L_ * H_ + hd;
    const float* Vb = g_V + (size_t)b * L_ * H_ + hd;

    #pragma unroll 1
    for (int half = 0; half < 2; half++) {
        const int t  = half ? (63 - tpair) : tpair;
        const int i0 = t * TQ;
        const int i  = i0 + q;
        const int nq = i + 1;       // causal: keys j in [0, nq)

        // --- per-warp setup: q vector (float2 per lane) + interval idxs ---
        const float2 qv =
            ((const float2*)(g_Q + ((size_t)(b * L_ + i)) * H_ + hd))[lane];
        const int* iv = interval + ((size_t)(b * L_ + i)) * L_;
        for (int j = lane; j < nq; j += 32) idxs[q][j] = iv[j];
        __syncwarp();

        // --- scores: s[j] = q . (K_j + E_RK[idx]) / 8 ---
        {
            int j = 0;
            for (; j + 2 <= nq; j += 2) {
                int ia = idxs[q][j], ib = idxs[q][j + 1];
                float2 k0 = ((const float2*)(Kb + (size_t)j * H_))[lane];
                float2 k1 = ((const float2*)(Kb + (size_t)(j + 1) * H_))[lane];
                float2 r0 = ((const float2*)(E_RK + (size_t)ia * H_ + hd))[lane];
                float2 r1 = ((const float2*)(E_RK + (size_t)ib * H_ + hd))[lane];
                float p0 = qv.x * (k0.x + r0.x) + qv.y * (k0.y + r0.y);
                float p1 = qv.x * (k1.x + r1.x) + qv.y * (k1.y + r1.y);
                #pragma unroll
                for (int off = 16; off > 0; off >>= 1) {
                    p0 += __shfl_xor_sync(0xffffffffu, p0, off);
                    p1 += __shfl_xor_sync(0xffffffffu, p1, off);
                }
                if (lane == 0) {
                    sc[q][j]     = p0 * 0.125f;
                    sc[q][j + 1] = p1 * 0.125f;
                }
            }
            if (j < nq) {
                int ia = idxs[q][j];
                float2 k0 = ((const float2*)(Kb + (size_t)j * H_))[lane];
                float2 r0 = ((const float2*)(E_RK + (size_t)ia * H_ + hd))[lane];
                float p0 = qv.x * (k0.x + r0.x) + qv.y * (k0.y + r0.y);
                #pragma unroll
                for (int off = 16; off > 0; off >>= 1)
                    p0 += __shfl_xor_sync(0xffffffffu, p0, off);
                if (lane == 0) sc[q][j] = p0 * 0.125f;
            }
        }
        __syncwarp();

        // --- softmax (warp-local) ---
        {
            float m = -INFINITY;
            for (int j = lane; j < nq; j += 32) m = fmaxf(m, sc[q][j]);
            #pragma unroll
            for (int off = 16; off > 0; off >>= 1)
                m = fmaxf(m, __shfl_xor_sync(0xffffffffu, m, off));
            float s = 0.f;
            for (int j = lane; j < nq; j += 32) {
                float e = __expf(sc[q][j] - m);
                sc[q][j] = e;
                s += e;
            }
            #pragma unroll
            for (int off = 16; off > 0; off >>= 1)
                s += __shfl_xor_sync(0xffffffffu, s, off);
            float inv = 1.f / s;
            for (int j = lane; j < nq; j += 32) sc[q][j] *= inv;
        }
        __syncwarp();

        // --- output: out[d] = sum_j w[j] * (V_j[d] + E_RV[idx][d]) ---
        {
            float2 acc0 = make_float2(0.f, 0.f);
            float2 acc1 = make_float2(0.f, 0.f);
            int j = 0;
            #pragma unroll 2
            for (; j + 2 <= nq; j += 2) {
                float w0 = sc[q][j];
                float w1 = sc[q][j + 1];
                int ia = idxs[q][j], ib = idxs[q][j + 1];
                float2 v0 = ((const float2*)(Vb + (size_t)j * H_))[lane];
                float2 v1 = ((const float2*)(Vb + (size_t)(j + 1) * H_))[lane];
                float2 r0 = ((const float2*)(E_RV + (size_t)ia * H_ + hd))[lane];
                float2 r1 = ((const float2*)(E_RV + (size_t)ib * H_ + hd))[lane];
                acc0.x = fmaf(w0, v0.x + r0.x, acc0.x);
                acc0.y = fmaf(w0, v0.y + r0.y, acc0.y);
                acc1.x = fmaf(w1, v1.x + r1.x, acc1.x);
                acc1.y = fmaf(w1, v1.y + r1.y, acc1.y);
            }
            if (j < nq) {
                float w0 = sc[q][j];
                int ia = idxs[q][j];
                float2 v0 = ((const float2*)(Vb + (size_t)j * H_))[lane];
                float2 r0 = ((const float2*)(E_RV + (size_t)ia * H_ + hd))[lane];
                acc0.x = fmaf(w0, v0.x + r0.x, acc0.x);
                acc0.y = fmaf(w0, v0.y + r0.y, acc0.y);
            }
            float2 out;
            out.x = acc0.x + acc1.x;
            out.y = acc0.y + acc1.y;
            ((float2*)(g_O + ((size_t)(b * L_ + i)) * H_ + hd))[lane] = out;
        }
        __syncwarp();
        // smem slots are warp-private (indexed by q=warp): no block sync needed
    }
}

// ---------------------------------------------------------------------------
// Kernel 3: output projection: out = O @ Wo^T + bo, NaN -> 0. grid = 128.
// ---------------------------------------------------------------------------
__global__ __launch_bounds__(128) void proj_kernel(
    const float* __restrict__ Wo, const float* __restrict__ bo,
    float* __restrict__ out)
{
    __shared__ float4 xs[TM][32];

    const int r0 = blockIdx.x * TM;
    const int o  = threadIdx.x;

    const float4* Xv = (const float4*)(g_O + (size_t)r0 * H_);
    #pragma unroll
    for (int t = 0; t < (TM * 32) / 128; t++)
        ((float4*)xs)[o + t * 128] = Xv[o + t * 128];
    __syncthreads();

    float acc[TM];
    {
        float bb = bo[o];
        #pragma unroll
        for (int rr = 0; rr < TM; rr++) acc[rr] = bb;
    }

    const float4* w4p = (const float4*)(Wo + (size_t)o * H_);
    #pragma unroll 4
    for (int c = 0; c < 32; c++) {
        float4 w = w4p[c];
        #pragma unroll
        for (int rr = 0; rr < TM; rr++) {
            float4 x = xs[rr][c];
            acc[rr] = fmaf(w.x, x.x, acc[rr]);
            acc[rr] = fmaf(w.y, x.y, acc[rr]);
            acc[rr] = fmaf(w.z, x.z, acc[rr]);
            acc[rr] = fmaf(w.w, x.w, acc[rr]);
        }
    }

    #pragma unroll
    for (int rr = 0; rr < TM; rr++) {
        float v = acc[rr];
        if (isnan(v)) v = 0.f;
        out[(size_t)(r0 + rr) * H_ + o] = v;
    }
}

// ---------------------------------------------------------------------------
extern "C" void kernel_launch(void* const* d_in, const int* in_sizes, int n_in,
                              void* d_out, int out_size)
{
    const float* query    = (const float*)d_in[0];
    const float* key      = (const float*)d_in[1];
    const float* value    = (const float*)d_in[2];
    const float* Wq       = (const float*)d_in[3];
    const float* bq       = (const float*)d_in[4];
    const float* Wk       = (const float*)d_in[5];
    const float* bk       = (const float*)d_in[6];
    const float* Wv       = (const float*)d_in[7];
    const float* bv       = (const float*)d_in[8];
    const float* Wo       = (const float*)d_in[9];
    const float* bo       = (const float*)d_in[10];
    const float* E_PK     = (const float*)d_in[11];
    const float* E_PV     = (const float*)d_in[12];
    const float* E_RK     = (const float*)d_in[13];
    const float* E_RV     = (const float*)d_in[14];
    const int*   poss     = (const int*)d_in[15];
    const int*   interval = (const int*)d_in[16];
    // d_in[17] = attn_mask (exactly tril; causal is hardcoded)

    float* out = (float*)d_out;

    dim3 qgrid((B_ * L_) / TM, 3);
    qkv_kernel<<<qgrid, 128>>>(
        query, key, value, Wq, bq, Wk, bk, Wv, bv, E_PK, E_PV, poss);

    dim3 agrid(L_ / TQ / 2, NH_, B_);   // (32, 2, 2) — paired tiles
    attn_kernel<<<agrid, 256>>>(E_RK, E_RV, interval);

    proj_kernel<<<(B_ * L_) / TM, 128>>>(Wo, bo, out);
}

// round 6
// speedup vs baseline: 1.5874x; 1.5874x over previous
#include <cuda_runtime.h>
#include <math.h>

#define B_  2
#define L_  512
#define H_  128
#define NH_ 2
#define DH_ 64
#define RV_ 257   // REL_VOCAB

// Scratch (allocation-free rule: __device__ globals)
__device__ float g_Q[B_ * L_ * H_];
__device__ float g_K[B_ * L_ * H_];
__device__ float g_V[B_ * L_ * H_];
__device__ float g_O[B_ * L_ * H_];

#define TM 4   // rows per GEMM block

// ---------------------------------------------------------------------------
// Kernel 1: fused QKV projections. grid = (256, 3). blockIdx.y selects matrix.
//   Y = X @ W^T + b  (+ E[pos] for K and V)
// 128 threads, one output channel each, TM rows, float4-vectorized.
// ---------------------------------------------------------------------------
__global__ __launch_bounds__(128) void qkv_kernel(
    const float* __restrict__ query, const float* __restrict__ key,
    const float* __restrict__ value,
    const float* __restrict__ Wq, const float* __restrict__ bq,
    const float* __restrict__ Wk, const float* __restrict__ bk,
    const float* __restrict__ Wv, const float* __restrict__ bv,
    const float* __restrict__ E_PK, const float* __restrict__ E_PV,
    const int* __restrict__ poss)
{
    const int m = blockIdx.y;
    const float *X, *W, *bias, *E;
    float* Y;
    if (m == 0)      { X = query; W = Wq; bias = bq; E = nullptr; Y = g_Q; }
    else if (m == 1) { X = key;   W = Wk; bias = bk; E = E_PK;    Y = g_K; }
    else             { X = value; W = Wv; bias = bv; E = E_PV;    Y = g_V; }

    __shared__ float4 xs[TM][32];   // TM rows x 128 floats

    const int r0 = blockIdx.x * TM;
    const int o  = threadIdx.x;     // output channel 0..127

    // TM*32 = 128 float4 elements, one per thread
    ((float4*)xs)[o] = ((const float4*)(X + (size_t)r0 * H_))[o];
    __syncthreads();

    float acc[TM];
    {
        float bb = bias[o];
        #pragma unroll
        for (int rr = 0; rr < TM; rr++) {
            acc[rr] = bb;
            if (E) acc[rr] += E[(size_t)poss[r0 + rr] * H_ + o];
        }
    }

    const float4* w4p = (const float4*)(W + (size_t)o * H_);
    #pragma unroll 8
    for (int c = 0; c < 32; c++) {
        float4 w = w4p[c];
        #pragma unroll
        for (int rr = 0; rr < TM; rr++) {
            float4 x = xs[rr][c];
            acc[rr] = fmaf(w.x, x.x, acc[rr]);
            acc[rr] = fmaf(w.y, x.y, acc[rr]);
            acc[rr] = fmaf(w.z, x.z, acc[rr]);
            acc[rr] = fmaf(w.w, x.w, acc[rr]);
        }
    }

    #pragma unroll
    for (int rr = 0; rr < TM; rr++)
        Y[(size_t)(r0 + rr) * H_ + o] = acc[rr];
}

// ---------------------------------------------------------------------------
// Kernel 2: attention, block per (b,h,i), 256 threads. No E_RK/E_RV gathers:
//   rs[r] = q . E_RK[r]           (dense coalesced sweep, r < 257)
//   s[j]  = (q . K_j + rs[idx[j]]) / 8     (idx lookup is 4B smem)
//   w     = softmax(s)
//   ws[r] = sum_{j: idx[j]==r} w[j]        (smem histogram)
//   out   = sum_j w[j] V_j  +  sum_r ws[r] E_RV[r]   (dense sweep)
// ---------------------------------------------------------------------------
__global__ __launch_bounds__(256) void attn_kernel(
    const float* __restrict__ E_RK, const float* __restrict__ E_RV,
    const int* __restrict__ interval)
{
    const int i = L_ - 1 - blockIdx.x;   // long queries first (wave balance)
    const int h = blockIdx.y;
    const int b = blockIdx.z;
    const int tid  = threadIdx.x;
    const int warp = tid >> 5;
    const int lane = tid & 31;
    const int hd = h * DH_;
    const int n = i + 1;                 // causal: keys j in [0, n)

    __shared__ float qs[DH_];
    __shared__ float rs[RV_ + 3];
    __shared__ float ws[RV_ + 3];
    __shared__ float sc[L_];
    __shared__ int   idxs[L_];
    __shared__ float red[256];

    // --- setup: q, interval idx row, zero histogram ---
    if (tid < DH_)
        qs[tid] = g_Q[((size_t)(b * L_ + i)) * H_ + hd + tid];
    {
        const int* iv = interval + ((size_t)(b * L_ + i)) * L_;
        for (int j = tid; j < n; j += 256) idxs[j] = iv[j];
    }
    for (int r = tid; r < RV_; r += 256) ws[r] = 0.f;
    __syncthreads();

    const float2 qv = ((const float2*)qs)[lane];

    // --- phase 1: rs[r] = q . E_RK[r, hd:hd+64]  (warp per r, stride 8) ---
    for (int r = warp; r < RV_; r += 8) {
        float2 e = ((const float2*)(E_RK + (size_t)r * H_ + hd))[lane];
        float p = qv.x * e.x + qv.y * e.y;
        #pragma unroll
        for (int off = 16; off > 0; off >>= 1)
            p += __shfl_xor_sync(0xffffffffu, p, off);
        if (lane == 0) rs[r] = p;
    }
    __syncthreads();

    // --- phase 2: scores s[j] = (q.K_j + rs[idx[j]]) / 8 ---
    {
        const float* Kb = g_K + (size_t)b * L_ * H_ + hd;
        for (int j = warp; j < n; j += 8) {
            float2 k = ((const float2*)(Kb + (size_t)j * H_))[lane];
            float p = qv.x * k.x + qv.y * k.y;
            #pragma unroll
            for (int off = 16; off > 0; off >>= 1)
                p += __shfl_xor_sync(0xffffffffu, p, off);
            if (lane == 0)
                sc[j] = 0.125f * (p + rs[idxs[j]]);
        }
    }
    __syncthreads();

    // --- phase 3: block softmax over sc[0..n) ---
    {
        float m = -INFINITY;
        for (int j = tid; j < n; j += 256) m = fmaxf(m, sc[j]);
        red[tid] = m;
        __syncthreads();
        #pragma unroll
        for (int s = 128; s > 0; s >>= 1) {
            if (tid < s) red[tid] = fmaxf(red[tid], red[tid + s]);
            __syncthreads();
        }
        m = red[0];
        __syncthreads();

        float sum = 0.f;
        for (int j = tid; j < n; j += 256) {
            float e = __expf(sc[j] - m);
            sc[j] = e;
            sum += e;
        }
        red[tid] = sum;
        __syncthreads();
        #pragma unroll
        for (int s = 128; s > 0; s >>= 1) {
            if (tid < s) red[tid] += red[tid + s];
            __syncthreads();
        }
        float inv = 1.f / red[0];
        __syncthreads();
        for (int j = tid; j < n; j += 256) sc[j] *= inv;
    }
    __syncthreads();

    // --- phase 4: histogram ws[r] = sum of weights with idx == r ---
    for (int j = tid; j < n; j += 256)
        atomicAdd(&ws[idxs[j]], sc[j]);
    __syncthreads();

    // --- phase 5: out[d] = sum_j w_j V_j[d] + sum_r ws[r] E_RV[r][d] ---
    {
        const int d = tid & 63;
        const int g = tid >> 6;
        const float* Vb = g_V + (size_t)b * L_ * H_ + hd;
        float acc = 0.f;
        for (int j = g; j < n; j += 4)
            acc = fmaf(sc[j], Vb[(size_t)j * H_ + d], acc);
        for (int r = g; r < RV_; r += 4)
            acc = fmaf(ws[r], E_RV[(size_t)r * H_ + hd + d], acc);
        red[g * 64 + d] = acc;
        __syncthreads();
        if (g == 0) {
            float o = red[d] + red[64 + d] + red[128 + d] + red[192 + d];
            g_O[((size_t)(b * L_ + i)) * H_ + hd + d] = o;
        }
    }
}

// ---------------------------------------------------------------------------
// Kernel 3: output projection: out = O @ Wo^T + bo, NaN -> 0. grid = 256.
// ---------------------------------------------------------------------------
__global__ __launch_bounds__(128) void proj_kernel(
    const float* __restrict__ Wo, const float* __restrict__ bo,
    float* __restrict__ out)
{
    __shared__ float4 xs[TM][32];

    const int r0 = blockIdx.x * TM;
    const int o  = threadIdx.x;

    ((float4*)xs)[o] = ((const float4*)(g_O + (size_t)r0 * H_))[o];
    __syncthreads();

    float acc[TM];
    {
        float bb = bo[o];
        #pragma unroll
        for (int rr = 0; rr < TM; rr++) acc[rr] = bb;
    }

    const float4* w4p = (const float4*)(Wo + (size_t)o * H_);
    #pragma unroll 8
    for (int c = 0; c < 32; c++) {
        float4 w = w4p[c];
        #pragma unroll
        for (int rr = 0; rr < TM; rr++) {
            float4 x = xs[rr][c];
            acc[rr] = fmaf(w.x, x.x, acc[rr]);
            acc[rr] = fmaf(w.y, x.y, acc[rr]);
            acc[rr] = fmaf(w.z, x.z, acc[rr]);
            acc[rr] = fmaf(w.w, x.w, acc[rr]);
        }
    }

    #pragma unroll
    for (int rr = 0; rr < TM; rr++) {
        float v = acc[rr];
        if (isnan(v)) v = 0.f;
        out[(size_t)(r0 + rr) * H_ + o] = v;
    }
}

// ---------------------------------------------------------------------------
extern "C" void kernel_launch(void* const* d_in, const int* in_sizes, int n_in,
                              void* d_out, int out_size)
{
    const float* query    = (const float*)d_in[0];
    const float* key      = (const float*)d_in[1];
    const float* value    = (const float*)d_in[2];
    const float* Wq       = (const float*)d_in[3];
    const float* bq       = (const float*)d_in[4];
    const float* Wk       = (const float*)d_in[5];
    const float* bk       = (const float*)d_in[6];
    const float* Wv       = (const float*)d_in[7];
    const float* bv       = (const float*)d_in[8];
    const float* Wo       = (const float*)d_in[9];
    const float* bo       = (const float*)d_in[10];
    const float* E_PK     = (const float*)d_in[11];
    const float* E_PV     = (const float*)d_in[12];
    const float* E_RK     = (const float*)d_in[13];
    const float* E_RV     = (const float*)d_in[14];
    const int*   poss     = (const int*)d_in[15];
    const int*   interval = (const int*)d_in[16];
    // d_in[17] = attn_mask (exactly tril; causal is hardcoded)

    float* out = (float*)d_out;

    dim3 qgrid((B_ * L_) / TM, 3);
    qkv_kernel<<<qgrid, 128>>>(
        query, key, value, Wq, bq, Wk, bk, Wv, bv, E_PK, E_PV, poss);

    dim3 agrid(L_, NH_, B_);
    attn_kernel<<<agrid, 256>>>(E_RK, E_RV, interval);

    proj_kernel<<<(B_ * L_) / TM, 128>>>(Wo, bo, out);
}

// round 7
// speedup vs baseline: 1.6024x; 1.0094x over previous
#include <cuda_runtime.h>
#include <math.h>

#define B_  2
#define L_  512
#define H_  128
#define NH_ 2
#define DH_ 64
#define RV_ 257   // REL_VOCAB

// Scratch (allocation-free rule: __device__ globals)
__device__ float g_Q[B_ * L_ * H_];
__device__ float g_K[B_ * L_ * H_];
__device__ float g_V[B_ * L_ * H_];
__device__ float g_O[B_ * L_ * H_];

#define TM 4   // rows per GEMM block

// ---------------------------------------------------------------------------
// Kernel 1: fused QKV projections. grid = (256, 3). blockIdx.y selects matrix.
//   Y = X @ W^T + b  (+ E[pos] for K and V)
// 128 threads, one output channel each, TM rows, float4-vectorized.
// ---------------------------------------------------------------------------
__global__ __launch_bounds__(128) void qkv_kernel(
    const float* __restrict__ query, const float* __restrict__ key,
    const float* __restrict__ value,
    const float* __restrict__ Wq, const float* __restrict__ bq,
    const float* __restrict__ Wk, const float* __restrict__ bk,
    const float* __restrict__ Wv, const float* __restrict__ bv,
    const float* __restrict__ E_PK, const float* __restrict__ E_PV,
    const int* __restrict__ poss)
{
    const int m = blockIdx.y;
    const float *X, *W, *bias, *E;
    float* Y;
    if (m == 0)      { X = query; W = Wq; bias = bq; E = nullptr; Y = g_Q; }
    else if (m == 1) { X = key;   W = Wk; bias = bk; E = E_PK;    Y = g_K; }
    else             { X = value; W = Wv; bias = bv; E = E_PV;    Y = g_V; }

    __shared__ float4 xs[TM][32];   // TM rows x 128 floats

    const int r0 = blockIdx.x * TM;
    const int o  = threadIdx.x;     // output channel 0..127

    // TM*32 = 128 float4 elements, one per thread
    ((float4*)xs)[o] = ((const float4*)(X + (size_t)r0 * H_))[o];
    __syncthreads();

    float acc[TM];
    {
        float bb = bias[o];
        #pragma unroll
        for (int rr = 0; rr < TM; rr++) {
            acc[rr] = bb;
            if (E) acc[rr] += E[(size_t)poss[r0 + rr] * H_ + o];
        }
    }

    const float4* w4p = (const float4*)(W + (size_t)o * H_);
    #pragma unroll 8
    for (int c = 0; c < 32; c++) {
        float4 w = w4p[c];
        #pragma unroll
        for (int rr = 0; rr < TM; rr++) {
            float4 x = xs[rr][c];
            acc[rr] = fmaf(w.x, x.x, acc[rr]);
            acc[rr] = fmaf(w.y, x.y, acc[rr]);
            acc[rr] = fmaf(w.z, x.z, acc[rr]);
            acc[rr] = fmaf(w.w, x.w, acc[rr]);
        }
    }

    #pragma unroll
    for (int rr = 0; rr < TM; rr++)
        Y[(size_t)(r0 + rr) * H_ + o] = acc[rr];
}

// ---------------------------------------------------------------------------
// Kernel 2: attention, block per (b,h,i), 256 threads. No E_RK/E_RV gathers:
//   rs[r] = q . E_RK[r]           (dense coalesced sweep, r < 257)
//   s[j]  = (q . K_j + rs[idx[j]]) / 8     (idx lookup is 4B smem)
//   w     = softmax(s)
//   ws[r] = sum_{j: idx[j]==r} w[j]        (smem histogram)
//   out   = sum_j w[j] V_j  +  sum_r ws[r] E_RV[r]   (dense sweep)
// ---------------------------------------------------------------------------
__global__ __launch_bounds__(256) void attn_kernel(
    const float* __restrict__ E_RK, const float* __restrict__ E_RV,
    const int* __restrict__ interval)
{
    const int i = L_ - 1 - blockIdx.x;   // long queries first (wave balance)
    const int h = blockIdx.y;
    const int b = blockIdx.z;
    const int tid  = threadIdx.x;
    const int warp = tid >> 5;
    const int lane = tid & 31;
    const int hd = h * DH_;
    const int n = i + 1;                 // causal: keys j in [0, n)

    __shared__ float qs[DH_];
    __shared__ float rs[RV_ + 3];
    __shared__ float ws[RV_ + 3];
    __shared__ float sc[L_];
    __shared__ int   idxs[L_];
    __shared__ float red[256];

    // --- setup: q, interval idx row, zero histogram ---
    if (tid < DH_)
        qs[tid] = g_Q[((size_t)(b * L_ + i)) * H_ + hd + tid];
    {
        const int* iv = interval + ((size_t)(b * L_ + i)) * L_;
        for (int j = tid; j < n; j += 256) idxs[j] = iv[j];
    }
    for (int r = tid; r < RV_; r += 256) ws[r] = 0.f;
    __syncthreads();

    const float2 qv = ((const float2*)qs)[lane];

    // --- phase 1: rs[r] = q . E_RK[r, hd:hd+64]  (warp per r, stride 8) ---
    for (int r = warp; r < RV_; r += 8) {
        float2 e = ((const float2*)(E_RK + (size_t)r * H_ + hd))[lane];
        float p = qv.x * e.x + qv.y * e.y;
        #pragma unroll
        for (int off = 16; off > 0; off >>= 1)
            p += __shfl_xor_sync(0xffffffffu, p, off);
        if (lane == 0) rs[r] = p;
    }
    __syncthreads();

    // --- phase 2: scores s[j] = (q.K_j + rs[idx[j]]) / 8 ---
    {
        const float* Kb = g_K + (size_t)b * L_ * H_ + hd;
        for (int j = warp; j < n; j += 8) {
            float2 k = ((const float2*)(Kb + (size_t)j * H_))[lane];
            float p = qv.x * k.x + qv.y * k.y;
            #pragma unroll
            for (int off = 16; off > 0; off >>= 1)
                p += __shfl_xor_sync(0xffffffffu, p, off);
            if (lane == 0)
                sc[j] = 0.125f * (p + rs[idxs[j]]);
        }
    }
    __syncthreads();

    // --- phase 3: block softmax over sc[0..n) ---
    {
        float m = -INFINITY;
        for (int j = tid; j < n; j += 256) m = fmaxf(m, sc[j]);
        red[tid] = m;
        __syncthreads();
        #pragma unroll
        for (int s = 128; s > 0; s >>= 1) {
            if (tid < s) red[tid] = fmaxf(red[tid], red[tid + s]);
            __syncthreads();
        }
        m = red[0];
        __syncthreads();

        float sum = 0.f;
        for (int j = tid; j < n; j += 256) {
            float e = __expf(sc[j] - m);
            sc[j] = e;
            sum += e;
        }
        red[tid] = sum;
        __syncthreads();
        #pragma unroll
        for (int s = 128; s > 0; s >>= 1) {
            if (tid < s) red[tid] += red[tid + s];
            __syncthreads();
        }
        float inv = 1.f / red[0];
        __syncthreads();
        for (int j = tid; j < n; j += 256) sc[j] *= inv;
    }
    __syncthreads();

    // --- phase 4: histogram ws[r] = sum of weights with idx == r ---
    for (int j = tid; j < n; j += 256)
        atomicAdd(&ws[idxs[j]], sc[j]);
    __syncthreads();

    // --- phase 5: out[d] = sum_j w_j V_j[d] + sum_r ws[r] E_RV[r][d] ---
    {
        const int d = tid & 63;
        const int g = tid >> 6;
        const float* Vb = g_V + (size_t)b * L_ * H_ + hd;
        float acc = 0.f;
        for (int j = g; j < n; j += 4)
            acc = fmaf(sc[j], Vb[(size_t)j * H_ + d], acc);
        for (int r = g; r < RV_; r += 4)
            acc = fmaf(ws[r], E_RV[(size_t)r * H_ + hd + d], acc);
        red[g * 64 + d] = acc;
        __syncthreads();
        if (g == 0) {
            float o = red[d] + red[64 + d] + red[128 + d] + red[192 + d];
            g_O[((size_t)(b * L_ + i)) * H_ + hd + d] = o;
        }
    }
}

// ---------------------------------------------------------------------------
// Kernel 3: output projection: out = O @ Wo^T + bo, NaN -> 0. grid = 256.
// ---------------------------------------------------------------------------
__global__ __launch_bounds__(128) void proj_kernel(
    const float* __restrict__ Wo, const float* __restrict__ bo,
    float* __restrict__ out)
{
    __shared__ float4 xs[TM][32];

    const int r0 = blockIdx.x * TM;
    const int o  = threadIdx.x;

    ((float4*)xs)[o] = ((const float4*)(g_O + (size_t)r0 * H_))[o];
    __syncthreads();

    float acc[TM];
    {
        float bb = bo[o];
        #pragma unroll
        for (int rr = 0; rr < TM; rr++) acc[rr] = bb;
    }

    const float4* w4p = (const float4*)(Wo + (size_t)o * H_);
    #pragma unroll 8
    for (int c = 0; c < 32; c++) {
        float4 w = w4p[c];
        #pragma unroll
        for (int rr = 0; rr < TM; rr++) {
            float4 x = xs[rr][c];
            acc[rr] = fmaf(w.x, x.x, acc[rr]);
            acc[rr] = fmaf(w.y, x.y, acc[rr]);
            acc[rr] = fmaf(w.z, x.z, acc[rr]);
            acc[rr] = fmaf(w.w, x.w, acc[rr]);
        }
    }

    #pragma unroll
    for (int rr = 0; rr < TM; rr++) {
        float v = acc[rr];
        if (isnan(v)) v = 0.f;
        out[(size_t)(r0 + rr) * H_ + o] = v;
    }
}

// ---------------------------------------------------------------------------
extern "C" void kernel_launch(void* const* d_in, const int* in_sizes, int n_in,
                              void* d_out, int out_size)
{
    const float* query    = (const float*)d_in[0];
    const float* key      = (const float*)d_in[1];
    const float* value    = (const float*)d_in[2];
    const float* Wq       = (const float*)d_in[3];
    const float* bq       = (const float*)d_in[4];
    const float* Wk       = (const float*)d_in[5];
    const float* bk       = (const float*)d_in[6];
    const float* Wv       = (const float*)d_in[7];
    const float* bv       = (const float*)d_in[8];
    const float* Wo       = (const float*)d_in[9];
    const float* bo       = (const float*)d_in[10];
    const float* E_PK     = (const float*)d_in[11];
    const float* E_PV     = (const float*)d_in[12];
    const float* E_RK     = (const float*)d_in[13];
    const float* E_RV     = (const float*)d_in[14];
    const int*   poss     = (const int*)d_in[15];
    const int*   interval = (const int*)d_in[16];
    // d_in[17] = attn_mask (exactly tril; causal is hardcoded)

    float* out = (float*)d_out;

    dim3 qgrid((B_ * L_) / TM, 3);
    qkv_kernel<<<qgrid, 128>>>(
        query, key, value, Wq, bq, Wk, bk, Wv, bv, E_PK, E_PV, poss);

    dim3 agrid(L_, NH_, B_);
    attn_kernel<<<agrid, 256>>>(E_RK, E_RV, interval);

    proj_kernel<<<(B_ * L_) / TM, 128>>>(Wo, bo, out);
}